// round 10
// baseline (speedup 1.0000x reference)
#include <cuda_runtime.h>

#define BB 256
#define TT 2048
#define HH 128
#define FC1N 64
#define RING 64
#define RPAD 132

// dynamic SMEM layout (float offsets)
#define OFF_X     0                          // padded x: TT*4
#define OFF_RING  (TT * 4)                   // RING*RPAD
#define OFF_WC    (OFF_RING + RING * RPAD)   // [3][HH]
#define OFF_P     (OFF_WC + 3 * HH)          // [2][192]
#define OFF_BC    (OFF_P + 2 * 192)
#define SMEM_FLOATS (OFF_BC + 4)

__device__ __forceinline__ unsigned long long fma2(unsigned long long a,
                                                   unsigned long long b,
                                                   unsigned long long c) {
    unsigned long long d;
    asm("fma.rn.f32x2 %0, %1, %2, %3;" : "=l"(d) : "l"(a), "l"(b), "l"(c));
    return d;
}
__device__ __forceinline__ unsigned long long add2(unsigned long long a,
                                                   unsigned long long b) {
    unsigned long long d;
    asm("add.rn.f32x2 %0, %1, %2;" : "=l"(d) : "l"(a), "l"(b));
    return d;
}
__device__ __forceinline__ unsigned long long pack2(float lo, float hi) {
    unsigned long long d;
    asm("mov.b64 %0, {%1, %2};" : "=l"(d) : "f"(lo), "f"(hi));
    return d;
}
__device__ __forceinline__ float2 unpack2(unsigned long long v) {
    float2 r;
    asm("mov.b64 {%0, %1}, %2;" : "=f"(r.x), "=f"(r.y) : "l"(v));
    return r;
}
__device__ __forceinline__ float tanh_fast(float x) {
    float y;
    asm("tanh.approx.f32 %0, %1;" : "=f"(y) : "f"(x));
    return y;
}

__global__ __launch_bounds__(128, 2)
void rnn_r8_kernel(const float* __restrict__ x,
                   const float* __restrict__ hidden,
                   const float* __restrict__ W_ih,
                   const float* __restrict__ W_hh,
                   const float* __restrict__ b_ih,
                   const float* __restrict__ b_hh,
                   const float* __restrict__ W_fc1,
                   const float* __restrict__ b_fc1,
                   const float* __restrict__ W_fc2,
                   const float* __restrict__ b_fc2,
                   float* __restrict__ out)
{
    extern __shared__ __align__(16) float sm[];
    float* xR   = sm + OFF_X;
    float* ring = sm + OFF_RING;
    float* wc   = sm + OFF_WC;
    float* pr   = sm + OFF_P;
    float* bc   = sm + OFF_BC;

    const int b = blockIdx.x;
    const int j = threadIdx.x;

    // ---- preload x[b] into padded SMEM (4 floats/step, xR[4t+c]) ----
    {
        const float4* g = (const float4*)(x + (size_t)b * TT * 3);
        #pragma unroll
        for (int i = 0; i < (TT * 3 / 4) / HH; i++) {    // 12 iters
            float4 v = g[i * HH + j];
            int idx = 4 * (i * HH + j);
            xR[(idx / 3) * 4 + idx % 3] = v.x; idx++;
            xR[(idx / 3) * 4 + idx % 3] = v.y; idx++;
            xR[(idx / 3) * 4 + idx % 3] = v.z; idx++;
            xR[(idx / 3) * 4 + idx % 3] = v.w;
        }
    }

    // ---- W_hh row j as packed f32x2 (128 regs) ----
    unsigned long long w[HH / 2];
    {
        const unsigned long long* wg = (const unsigned long long*)(W_hh + j * HH);
        #pragma unroll
        for (int i = 0; i < HH / 2; i++) w[i] = wg[i];
    }

    const float wih0 = W_ih[j * 3 + 0];
    const float wih1 = W_ih[j * 3 + 1];
    const float wih2 = W_ih[j * 3 + 2];
    const float bias = b_ih[j] + b_hh[j];

    // ---- collapsed FC head: wc[o][j] = sum_f W_fc2[o][f]*W_fc1[f][j] ----
    {
        float c0 = 0.f, c1 = 0.f, c2 = 0.f;
        #pragma unroll 4
        for (int f = 0; f < FC1N; f++) {
            float v = W_fc1[f * HH + j];
            c0 = fmaf(W_fc2[0 * FC1N + f], v, c0);
            c1 = fmaf(W_fc2[1 * FC1N + f], v, c1);
            c2 = fmaf(W_fc2[2 * FC1N + f], v, c2);
        }
        wc[0 * HH + j] = c0; wc[1 * HH + j] = c1; wc[2 * HH + j] = c2;
    }
    if (j < 3) {
        float s = 0.f;
        #pragma unroll 8
        for (int f = 0; f < FC1N; f++)
            s = fmaf(W_fc2[j * FC1N + f], b_fc1[f], s);
        bc[j] = s + b_fc2[j];
    }

    // initial hidden state in slot RING-1 (read by ts=0 of chunk 0)
    ring[(RING - 1) * RPAD + j] = hidden[b * HH + j];
    __syncthreads();

    const int g2 = j >> 6;      // FC k-half (0/1)
    const int sl = j & 63;      // FC slot
    float* outb = out + (size_t)b * TT * 3;

    float hv = 0.f, xp, xp_n;
    {   // xp for t = 0
        const float4 xq = *(const float4*)(xR);
        xp = fmaf(xq.z, wih2, fmaf(xq.y, wih1, fmaf(xq.x, wih0, bias)));
    }

    for (int tc = 0; tc < TT / RING; tc++) {
        #pragma unroll 1
        for (int ts = 0; ts < RING; ts++) {
            const int t = tc * RING + ts;

            // 128-wide dot; xp pre-folded into accumulator 0
            const ulonglong2* hp =
                (const ulonglong2*)(ring + ((ts - 1) & (RING - 1)) * RPAD);
            unsigned long long a0 = pack2(xp, 0.f);
            unsigned long long a1 = 0ull, a2 = 0ull, a3 = 0ull;
            #pragma unroll
            for (int i = 0; i < 16; i++) {
                ulonglong2 ha = hp[2 * i];
                ulonglong2 hb = hp[2 * i + 1];
                a0 = fma2(w[4 * i + 0], ha.x, a0);
                a1 = fma2(w[4 * i + 1], ha.y, a1);
                a2 = fma2(w[4 * i + 2], hb.x, a2);
                a3 = fma2(w[4 * i + 3], hb.y, a3);
            }
            unsigned long long s2 = add2(add2(a0, a1), add2(a2, a3));
            float2 f = unpack2(s2);

            hv = tanh_fast(f.x + f.y);
            ring[ts * RPAD + j] = hv;

            // prefetch next xp BEFORE the barrier (hides in tail shadow)
            const float4 xq = *(const float4*)(xR + 4 * (t + 1));
            xp_n = fmaf(xq.z, wih2, fmaf(xq.y, wih1, fmaf(xq.x, wih0, bias)));

            __syncthreads();
            xp = xp_n;
        }

        // ---- FC drain: 64 slots -> 192 outputs, once per 64 steps ----
        {
            // thread (g2, sl): dot over k in [g2*64, g2*64+64) for slot sl
            const float4* h4 = (const float4*)(ring + sl * RPAD + g2 * 64);
            const float4* w0 = (const float4*)(wc + 0 * HH + g2 * 64);
            const float4* w1 = (const float4*)(wc + 1 * HH + g2 * 64);
            const float4* w2 = (const float4*)(wc + 2 * HH + g2 * 64);
            float p0 = 0.f, p1 = 0.f, p2 = 0.f;
            #pragma unroll
            for (int i = 0; i < 16; i++) {
                float4 v = h4[i];
                float4 u0 = w0[i], u1 = w1[i], u2 = w2[i];
                p0 = fmaf(v.x, u0.x, fmaf(v.y, u0.y, fmaf(v.z, u0.z, fmaf(v.w, u0.w, p0))));
                p1 = fmaf(v.x, u1.x, fmaf(v.y, u1.y, fmaf(v.z, u1.z, fmaf(v.w, u1.w, p1))));
                p2 = fmaf(v.x, u2.x, fmaf(v.y, u2.y, fmaf(v.z, u2.z, fmaf(v.w, u2.w, p2))));
            }
            pr[g2 * 192 + sl * 3 + 0] = p0;
            pr[g2 * 192 + sl * 3 + 1] = p1;
            pr[g2 * 192 + sl * 3 + 2] = p2;
            __syncthreads();

            // 192 outputs, 128 threads: 2 passes (second covers j<64)
            {
                float v = pr[j] + pr[192 + j] + bc[j % 3];
                outb[(size_t)tc * (RING * 3) + j] = v;
            }
            if (j < 64) {
                int o = j + 128;
                float v = pr[o] + pr[192 + o] + bc[o % 3];
                outb[(size_t)tc * (RING * 3) + o] = v;
            }
            // pr is rewritten only after 64 more per-step barriers; ring slot 0
            // is rewritten only after the next step's barrier. No extra sync.
        }
    }

    // final hidden state
    out[(size_t)BB * TT * 3 + b * HH + j] = hv;
}

extern "C" void kernel_launch(void* const* d_in, const int* in_sizes, int n_in,
                              void* d_out, int out_size) {
    const float* x      = (const float*)d_in[0];
    const float* hidden = (const float*)d_in[1];
    const float* W_ih   = (const float*)d_in[2];
    const float* W_hh   = (const float*)d_in[3];
    const float* b_ih   = (const float*)d_in[4];
    const float* b_hh   = (const float*)d_in[5];
    const float* W_fc1  = (const float*)d_in[6];
    const float* b_fc1  = (const float*)d_in[7];
    const float* W_fc2  = (const float*)d_in[8];
    const float* b_fc2  = (const float*)d_in[9];
    float* out = (float*)d_out;

    const int smem_bytes = SMEM_FLOATS * sizeof(float);
    static bool attr_set = false;
    if (!attr_set) {
        cudaFuncSetAttribute(rnn_r8_kernel,
                             cudaFuncAttributeMaxDynamicSharedMemorySize,
                             smem_bytes);
        attr_set = true;
    }
    rnn_r8_kernel<<<BB, HH, smem_bytes>>>(
        x, hidden, W_ih, W_hh, b_ih, b_hh,
        W_fc1, b_fc1, W_fc2, b_fc2, out);
}

// round 11
// speedup vs baseline: 1.0368x; 1.0368x over previous
#include <cuda_runtime.h>

#define BB 256
#define TT 2048
#define HH 128
#define FC1N 64
#define RING 32
#define RPAD 132

// dynamic SMEM layout (float offsets)
#define OFF_X     0                          // TT*3
#define OFF_RING  (TT * 3)                   // RING*RPAD
#define OFF_WC    (OFF_RING + RING * RPAD)   // [3][HH]
#define OFF_P     (OFF_WC + 3 * HH)          // [4][96]
#define OFF_BC    (OFF_P + 4 * 96)
#define SMEM_FLOATS (OFF_BC + 4)

__device__ __forceinline__ unsigned long long fma2(unsigned long long a,
                                                   unsigned long long b,
                                                   unsigned long long c) {
    unsigned long long d;
    asm("fma.rn.f32x2 %0, %1, %2, %3;" : "=l"(d) : "l"(a), "l"(b), "l"(c));
    return d;
}
__device__ __forceinline__ unsigned long long add2(unsigned long long a,
                                                   unsigned long long b) {
    unsigned long long d;
    asm("add.rn.f32x2 %0, %1, %2;" : "=l"(d) : "l"(a), "l"(b));
    return d;
}
__device__ __forceinline__ unsigned long long pack2(float lo, float hi) {
    unsigned long long d;
    asm("mov.b64 %0, {%1, %2};" : "=l"(d) : "f"(lo), "f"(hi));
    return d;
}
__device__ __forceinline__ float2 unpack2(unsigned long long v) {
    float2 r;
    asm("mov.b64 {%0, %1}, %2;" : "=f"(r.x), "=f"(r.y) : "l"(v));
    return r;
}
__device__ __forceinline__ float tanh_fast(float x) {
    float y;
    asm("tanh.approx.f32 %0, %1;" : "=f"(y) : "f"(x));
    return y;
}

// one recurrence step; RD/WR are float* with compile-time-constant offsets
// from a loop-invariant (or 4-step-strided) base pointer.
#define STEP(RD, WR, TIDX)                                                  \
    {                                                                       \
        const float xv0 = x_sh[3 * (TIDX) + 0];                             \
        const float xv1 = x_sh[3 * (TIDX) + 1];                             \
        const float xv2 = x_sh[3 * (TIDX) + 2];                             \
        float xp = fmaf(xv2, wih2, fmaf(xv1, wih1, fmaf(xv0, wih0, bias))); \
        const ulonglong2* hp = (const ulonglong2*)(RD);                     \
        unsigned long long a0 = pack2(xp, 0.f);                             \
        unsigned long long a1 = 0ull, a2 = 0ull, a3 = 0ull;                 \
        _Pragma("unroll")                                                   \
        for (int i = 0; i < 16; i++) {                                      \
            ulonglong2 ha = hp[2 * i];                                      \
            ulonglong2 hb = hp[2 * i + 1];                                  \
            a0 = fma2(w[4 * i + 0], ha.x, a0);                              \
            a1 = fma2(w[4 * i + 1], ha.y, a1);                              \
            a2 = fma2(w[4 * i + 2], hb.x, a2);                              \
            a3 = fma2(w[4 * i + 3], hb.y, a3);                              \
        }                                                                   \
        unsigned long long s2 = add2(add2(a0, a1), add2(a2, a3));           \
        float2 f = unpack2(s2);                                             \
        hv = tanh_fast(f.x + f.y);                                          \
        (WR)[j] = hv;                                                       \
        __syncthreads();                                                    \
    }

__global__ __launch_bounds__(128, 2)
void rnn_r11_kernel(const float* __restrict__ x,
                    const float* __restrict__ hidden,
                    const float* __restrict__ W_ih,
                    const float* __restrict__ W_hh,
                    const float* __restrict__ b_ih,
                    const float* __restrict__ b_hh,
                    const float* __restrict__ W_fc1,
                    const float* __restrict__ b_fc1,
                    const float* __restrict__ W_fc2,
                    const float* __restrict__ b_fc2,
                    float* __restrict__ out)
{
    extern __shared__ __align__(16) float sm[];
    float* x_sh = sm + OFF_X;
    float* ring = sm + OFF_RING;
    float* wc   = sm + OFF_WC;
    float* pr   = sm + OFF_P;
    float* bc   = sm + OFF_BC;

    const int b = blockIdx.x;
    const int j = threadIdx.x;

    // ---- preload x[b] (coalesced float4, 12 iters) ----
    {
        const float4* g = (const float4*)(x + (size_t)b * TT * 3);
        float4* s = (float4*)x_sh;
        #pragma unroll
        for (int i = 0; i < (TT * 3 / 4) / HH; i++)
            s[i * HH + j] = g[i * HH + j];
    }

    // ---- W_hh row j as packed f32x2 (128 regs) ----
    unsigned long long w[HH / 2];
    {
        const unsigned long long* wg = (const unsigned long long*)(W_hh + j * HH);
        #pragma unroll
        for (int i = 0; i < HH / 2; i++) w[i] = wg[i];
    }

    const float wih0 = W_ih[j * 3 + 0];
    const float wih1 = W_ih[j * 3 + 1];
    const float wih2 = W_ih[j * 3 + 2];
    const float bias = b_ih[j] + b_hh[j];

    // ---- collapsed FC head: wc[o][j] = sum_f W_fc2[o][f]*W_fc1[f][j] ----
    {
        float c0 = 0.f, c1 = 0.f, c2 = 0.f;
        #pragma unroll 4
        for (int f = 0; f < FC1N; f++) {
            float v = W_fc1[f * HH + j];
            c0 = fmaf(W_fc2[0 * FC1N + f], v, c0);
            c1 = fmaf(W_fc2[1 * FC1N + f], v, c1);
            c2 = fmaf(W_fc2[2 * FC1N + f], v, c2);
        }
        wc[0 * HH + j] = c0; wc[1 * HH + j] = c1; wc[2 * HH + j] = c2;
    }
    if (j < 3) {
        float s = 0.f;
        #pragma unroll 8
        for (int f = 0; f < FC1N; f++)
            s = fmaf(W_fc2[j * FC1N + f], b_fc1[f], s);
        bc[j] = s + b_fc2[j];
    }

    // initial hidden state in slot RING-1 (t = -1)
    ring[(RING - 1) * RPAD + j] = hidden[b * HH + j];
    __syncthreads();

    const int kg = j >> 5;
    const int tl = j & 31;
    float* outb = out + (size_t)b * TT * 3;

    float hv = 0.f;

    for (int tc = 0; tc < TT / RING; tc++) {
        const int t0 = tc * RING;

        // ---- group 0 (ts 0..3): first read is prev chunk's slot 31 ----
        STEP(ring + 31 * RPAD, ring,            t0 + 0)
        STEP(ring,             ring + 1 * RPAD, t0 + 1)
        STEP(ring + 1 * RPAD,  ring + 2 * RPAD, t0 + 2)
        STEP(ring + 2 * RPAD,  ring + 3 * RPAD, t0 + 3)

        // ---- groups 1..7: all offsets constant from 4-step base ----
        #pragma unroll 1
        for (int g = 1; g < 8; g++) {
            float* bp = ring + g * (4 * RPAD);
            const int tb = t0 + 4 * g;
            STEP(bp - RPAD,     bp,             tb + 0)
            STEP(bp,            bp + 1 * RPAD,  tb + 1)
            STEP(bp + 1 * RPAD, bp + 2 * RPAD,  tb + 2)
            STEP(bp + 2 * RPAD, bp + 3 * RPAD,  tb + 3)
        }

        // ---- FC drain (R3-identical): slots 0..31 -> 96 outputs ----
        {
            const float4* w0 = (const float4*)(wc + 0 * HH + kg * 32);
            const float4* w1 = (const float4*)(wc + 1 * HH + kg * 32);
            const float4* w2 = (const float4*)(wc + 2 * HH + kg * 32);
            const float4* h4 = (const float4*)(ring + tl * RPAD + kg * 32);
            float p0 = 0.f, p1 = 0.f, p2 = 0.f;
            #pragma unroll
            for (int i = 0; i < 8; i++) {
                float4 v = h4[i];
                float4 u0 = w0[i], u1 = w1[i], u2 = w2[i];
                p0 = fmaf(v.x, u0.x, fmaf(v.y, u0.y, fmaf(v.z, u0.z, fmaf(v.w, u0.w, p0))));
                p1 = fmaf(v.x, u1.x, fmaf(v.y, u1.y, fmaf(v.z, u1.z, fmaf(v.w, u1.w, p1))));
                p2 = fmaf(v.x, u2.x, fmaf(v.y, u2.y, fmaf(v.z, u2.z, fmaf(v.w, u2.w, p2))));
            }
            pr[kg * 96 + tl * 3 + 0] = p0;
            pr[kg * 96 + tl * 3 + 1] = p1;
            pr[kg * 96 + tl * 3 + 2] = p2;
            __syncthreads();

            if (j < 96) {
                float v = pr[j] + pr[96 + j] + pr[192 + j] + pr[288 + j] + bc[j % 3];
                outb[(size_t)t0 * 3 + j] = v;
            }
            // ring slot 0 is rewritten only after the next step's barrier;
            // pr is rewritten only after 32 more barriers. No extra sync.
        }
    }

    // final hidden state
    out[(size_t)BB * TT * 3 + b * HH + j] = hv;
}

extern "C" void kernel_launch(void* const* d_in, const int* in_sizes, int n_in,
                              void* d_out, int out_size) {
    const float* x      = (const float*)d_in[0];
    const float* hidden = (const float*)d_in[1];
    const float* W_ih   = (const float*)d_in[2];
    const float* W_hh   = (const float*)d_in[3];
    const float* b_ih   = (const float*)d_in[4];
    const float* b_hh   = (const float*)d_in[5];
    const float* W_fc1  = (const float*)d_in[6];
    const float* b_fc1  = (const float*)d_in[7];
    const float* W_fc2  = (const float*)d_in[8];
    const float* b_fc2  = (const float*)d_in[9];
    float* out = (float*)d_out;

    const int smem_bytes = SMEM_FLOATS * sizeof(float);
    static bool attr_set = false;
    if (!attr_set) {
        cudaFuncSetAttribute(rnn_r11_kernel,
                             cudaFuncAttributeMaxDynamicSharedMemorySize,
                             smem_bytes);
        attr_set = true;
    }
    rnn_r11_kernel<<<BB, HH, smem_bytes>>>(
        x, hidden, W_ih, W_hh, b_ih, b_hh,
        W_fc1, b_fc1, W_fc2, b_fc2, out);
}

// round 12
// speedup vs baseline: 1.0776x; 1.0393x over previous
#include <cuda_runtime.h>

#define BB 256
#define TT 2048
#define HH 128
#define FC1N 64
#define RING 32          // ring depth (steps per FC chunk)
#define RPAD 132         // floats per ring row (16B-aligned, 4-way FC conflict)

__device__ __forceinline__ unsigned long long fma2(unsigned long long a,
                                                   unsigned long long b,
                                                   unsigned long long c) {
    unsigned long long d;
    asm("fma.rn.f32x2 %0, %1, %2, %3;" : "=l"(d) : "l"(a), "l"(b), "l"(c));
    return d;
}
__device__ __forceinline__ unsigned long long add2(unsigned long long a,
                                                   unsigned long long b) {
    unsigned long long d;
    asm("add.rn.f32x2 %0, %1, %2;" : "=l"(d) : "l"(a), "l"(b));
    return d;
}
__device__ __forceinline__ unsigned long long pack2(float lo, float hi) {
    unsigned long long d;
    asm("mov.b64 %0, {%1, %2};" : "=l"(d) : "f"(lo), "f"(hi));
    return d;
}
__device__ __forceinline__ float2 unpack2(unsigned long long v) {
    float2 r;
    asm("mov.b64 {%0, %1}, %2;" : "=f"(r.x), "=f"(r.y) : "l"(v));
    return r;
}
__device__ __forceinline__ float tanh_fast(float x) {
    float y;
    asm("tanh.approx.f32 %0, %1;" : "=f"(y) : "f"(x));
    return y;
}

__global__ __launch_bounds__(128, 2)
void rnn_fused_kernel(const float* __restrict__ x,
                      const float* __restrict__ hidden,
                      const float* __restrict__ W_ih,
                      const float* __restrict__ W_hh,
                      const float* __restrict__ b_ih,
                      const float* __restrict__ b_hh,
                      const float* __restrict__ W_fc1,
                      const float* __restrict__ b_fc1,
                      const float* __restrict__ W_fc2,
                      const float* __restrict__ b_fc2,
                      float* __restrict__ out)
{
    __shared__ __align__(16) float x_sh[TT * 3];            // 24 KB
    __shared__ __align__(16) float h_ring[RING * RPAD];     // 16.5 KB
    __shared__ __align__(16) float wc_sh[3][HH];            // collapsed fc2@fc1
    __shared__ float part_sh[4][RING * 3];                  // FC partials
    __shared__ float bc_sh[3];

    const int b = blockIdx.x;
    const int j = threadIdx.x;          // hidden unit owned by this thread

    // ---- preload x[b] into SMEM (coalesced float4, 12 iters) ----
    {
        const float4* xg = (const float4*)(x + (size_t)b * TT * 3);
        float4* xs = (float4*)x_sh;
        #pragma unroll
        for (int i = 0; i < (TT * 3 / 4) / HH; i++)
            xs[i * HH + j] = xg[i * HH + j];
    }

    // ---- W_hh row j into registers as packed f32x2 (64 regs) ----
    unsigned long long w[HH / 2];
    {
        const unsigned long long* wg = (const unsigned long long*)(W_hh + j * HH);
        #pragma unroll
        for (int i = 0; i < HH / 2; i++) w[i] = wg[i];
    }

    const float wih0 = W_ih[j * 3 + 0];
    const float wih1 = W_ih[j * 3 + 1];
    const float wih2 = W_ih[j * 3 + 2];
    const float bias = b_ih[j] + b_hh[j];

    // ---- collapse FC head: wc[o][j] = sum_f W_fc2[o][f] * W_fc1[f][j] ----
    {
        float wc0 = 0.f, wc1 = 0.f, wc2 = 0.f;
        #pragma unroll 4
        for (int f = 0; f < FC1N; f++) {
            float v = W_fc1[f * HH + j];
            wc0 = fmaf(W_fc2[0 * FC1N + f], v, wc0);
            wc1 = fmaf(W_fc2[1 * FC1N + f], v, wc1);
            wc2 = fmaf(W_fc2[2 * FC1N + f], v, wc2);
        }
        wc_sh[0][j] = wc0; wc_sh[1][j] = wc1; wc_sh[2][j] = wc2;
    }
    if (j < 3) {
        float s = 0.f;
        #pragma unroll 8
        for (int f = 0; f < FC1N; f++)
            s = fmaf(W_fc2[j * FC1N + f], b_fc1[f], s);
        bc_sh[j] = s + b_fc2[j];
    }

    // ---- initial hidden state lives in slot RING-1 (t = -1) ----
    h_ring[(RING - 1) * RPAD + j] = hidden[b * HH + j];
    __syncthreads();

    const int kg = j >> 5;        // FC k-group (0..3)
    const int tl = j & 31;        // FC local timestep
    float* outb = out + (size_t)b * TT * 3;

    float hv = 0.f;
    for (int t = 0; t < TT; t++) {
        // x projection (independent of h — schedule first)
        const float xv0 = x_sh[3 * t + 0];
        const float xv1 = x_sh[3 * t + 1];
        const float xv2 = x_sh[3 * t + 2];
        float xp = fmaf(xv2, wih2, fmaf(xv1, wih1, fmaf(xv0, wih0, bias)));

        // 128-wide dot(W_j, h_prev): 4 chains x 16 packed FMAs (broadcast LDS)
        // xp pre-folded into accumulator 0 (removes one serial fadd from tail)
        const ulonglong2* hp =
            (const ulonglong2*)(h_ring + ((t - 1) & (RING - 1)) * RPAD);
        unsigned long long a0 = pack2(xp, 0.f);
        unsigned long long a1 = 0ull, a2 = 0ull, a3 = 0ull;
        #pragma unroll
        for (int i = 0; i < 16; i++) {
            ulonglong2 ha = hp[2 * i];
            ulonglong2 hb = hp[2 * i + 1];
            a0 = fma2(w[4 * i + 0], ha.x, a0);
            a1 = fma2(w[4 * i + 1], ha.y, a1);
            a2 = fma2(w[4 * i + 2], hb.x, a2);
            a3 = fma2(w[4 * i + 3], hb.y, a3);
        }
        unsigned long long s2 = add2(add2(a0, a1), add2(a2, a3));
        float2 f = unpack2(s2);

        hv = tanh_fast(f.x + f.y);
        h_ring[(t & (RING - 1)) * RPAD + j] = hv;
        __syncthreads();

        // ---- amortized FC head: every RING steps, drain slots 0..31 ----
        if ((t & (RING - 1)) == (RING - 1)) {
            const float4* h4 = (const float4*)(h_ring + tl * RPAD + kg * 32);
            const float4* w0 = (const float4*)(wc_sh[0] + kg * 32);
            const float4* w1 = (const float4*)(wc_sh[1] + kg * 32);
            const float4* w2 = (const float4*)(wc_sh[2] + kg * 32);
            float p0 = 0.f, p1 = 0.f, p2 = 0.f;
            #pragma unroll
            for (int i = 0; i < 8; i++) {
                float4 hq = h4[i];
                float4 wa = w0[i], wb = w1[i], wcc = w2[i];
                p0 = fmaf(hq.x, wa.x, fmaf(hq.y, wa.y, fmaf(hq.z, wa.z, fmaf(hq.w, wa.w, p0))));
                p1 = fmaf(hq.x, wb.x, fmaf(hq.y, wb.y, fmaf(hq.z, wb.z, fmaf(hq.w, wb.w, p1))));
                p2 = fmaf(hq.x, wcc.x, fmaf(hq.y, wcc.y, fmaf(hq.z, wcc.z, fmaf(hq.w, wcc.w, p2))));
            }
            part_sh[kg][tl * 3 + 0] = p0;
            part_sh[kg][tl * 3 + 1] = p1;
            part_sh[kg][tl * 3 + 2] = p2;
            __syncthreads();

            if (j < RING * 3) {
                float v = part_sh[0][j] + part_sh[1][j] +
                          part_sh[2][j] + part_sh[3][j] + bc_sh[j % 3];
                outb[(size_t)(t - (RING - 1)) * 3 + j] = v;   // 96 coalesced floats
            }
            // ring slot 0 is rewritten only after the next step's barrier;
            // partials are rewritten only after 32 more barriers. No extra sync.
        }
    }

    // final hidden state -> second output region
    out[(size_t)BB * TT * 3 + b * HH + j] = hv;
}

extern "C" void kernel_launch(void* const* d_in, const int* in_sizes, int n_in,
                              void* d_out, int out_size) {
    const float* x      = (const float*)d_in[0];
    const float* hidden = (const float*)d_in[1];
    const float* W_ih   = (const float*)d_in[2];
    const float* W_hh   = (const float*)d_in[3];
    const float* b_ih   = (const float*)d_in[4];
    const float* b_hh   = (const float*)d_in[5];
    const float* W_fc1  = (const float*)d_in[6];
    const float* b_fc1  = (const float*)d_in[7];
    const float* W_fc2  = (const float*)d_in[8];
    const float* b_fc2  = (const float*)d_in[9];
    float* out = (float*)d_out;

    rnn_fused_kernel<<<BB, HH>>>(x, hidden, W_ih, W_hh, b_ih, b_hh,
                                 W_fc1, b_fc1, W_fc2, b_fc2, out);
}